// round 5
// baseline (speedup 1.0000x reference)
#include <cuda_runtime.h>
#include <cuda_bf16.h>
#include <math.h>
#include <stdint.h>

#define BB 64
#define TT 4096
#define DD 256
#define UU 256

// ---------------- device-global scratch (allocation-free rule) -------------
__device__ float g_scores[BB * TT];
__device__ float g_cpart[16 * BB * DD];
__device__ __align__(16) __nv_bfloat16 g_WhT[UU * DD];   // (W1+W2)^T hi, [n][k]
__device__ __align__(16) __nv_bfloat16 g_WlT[UU * DD];   // (W1+W2)^T lo, [n][k]

// ---------------- smem layout for score kernel -----------------------------
#define KC      32                 // k per W chunk
#define ARB     528                // A row stride bytes (512 data + 16 pad)
#define A_H     0
#define A_L     67584              // 128 * 528
#define WROWB   80                 // W row stride bytes (64 data + 16 pad)
#define W_BASE  135168             // A_L + 67584
#define W_LOFF  20480              // hi -> lo offset within a stage
#define W_STAGE 40960              // stage stride (hi+lo)
#define RED_OFF 217088             // W_BASE + 2*W_STAGE
#define SV_OFF  221184             // RED_OFF + 4096
#define SM_TOTAL 222208

// ---------------- PTX helpers (plain sm_103-legal: no 'a' features) --------
__device__ __forceinline__ uint32_t smem_u32(const void* p) {
    uint32_t a;
    asm("{ .reg .u64 t; cvta.to.shared.u64 t, %1; cvt.u32.u64 %0, t; }"
        : "=r"(a) : "l"(p));
    return a;
}
__device__ __forceinline__ void ldm4(uint32_t* r, uint32_t addr) {
    asm volatile("ldmatrix.sync.aligned.m8n8.x4.shared.b16 {%0,%1,%2,%3}, [%4];"
                 : "=r"(r[0]), "=r"(r[1]), "=r"(r[2]), "=r"(r[3]) : "r"(addr));
}
__device__ __forceinline__ void mma16816(float* c, const uint32_t* a, const uint32_t* b) {
    asm volatile(
        "mma.sync.aligned.m16n8k16.row.col.f32.bf16.bf16.f32 "
        "{%0,%1,%2,%3},{%4,%5,%6,%7},{%8,%9},{%0,%1,%2,%3};"
        : "+f"(c[0]), "+f"(c[1]), "+f"(c[2]), "+f"(c[3])
        : "r"(a[0]), "r"(a[1]), "r"(a[2]), "r"(a[3]), "r"(b[0]), "r"(b[1]));
}
__device__ __forceinline__ void cpa16(uint32_t dst, const void* src) {
    asm volatile("cp.async.ca.shared.global [%0], [%1], 16;" :: "r"(dst), "l"(src));
}
#define CP_COMMIT() asm volatile("cp.async.commit_group;" ::: "memory")
#define CP_WAIT0()  asm volatile("cp.async.wait_group 0;" ::: "memory")

__device__ __forceinline__ uint32_t pack_bf2(float a, float b) {
    __nv_bfloat162 t = __floats2bfloat162_rn(a, b);
    return *(uint32_t*)&t;
}
__device__ __forceinline__ float fast_tanh(float q) {
    float e = __expf(2.f * q);
    return 1.f - __fdividef(2.f, e + 1.f);   // exact limits at +/-inf
}

// ---------------- phase 0: fuse + split + transpose weights ----------------
__global__ void prep_w(const float* __restrict__ W1, const float* __restrict__ W2)
{
    int idx = blockIdx.x * 256 + threadIdx.x;   // idx = k*256 + u
    int k = idx >> 8, u = idx & 255;
    float w = W1[idx] + W2[idx];
    __nv_bfloat16 h = __float2bfloat16(w);
    __nv_bfloat16 l = __float2bfloat16(w - __bfloat162float(h));
    g_WhT[u * DD + k] = h;
    g_WlT[u * DD + k] = l;
}

// ---------------- phase 1: HMMA GEMM + tanh/v epilogue ---------------------
// 512 threads, tile M=128 x N=256. A (X) hi/lo resident in smem for all K;
// W streamed in 32-k chunks, double-buffered cp.async.
__global__ void __launch_bounds__(512, 1)
score_mma_kernel(const float* __restrict__ X, const float* __restrict__ v)
{
    extern __shared__ char smem[];
    const uint32_t sb = smem_u32(smem);
    const int tid  = threadIdx.x;
    const int wid  = tid >> 5, lane = tid & 31;
    const int wg   = wid >> 3, wn = wid & 7;
    const long row0 = (long)blockIdx.x * 128;

    if (tid < 256) ((float*)(smem + SV_OFF))[tid] = v[tid];

    // ---- prologue: load + split the whole A tile (128 rows x 256 k)
    {
        const int ar  = tid >> 2;          // row 0..127
        const int akg = tid & 3;           // 64-float segment
        const float* ap = X + (row0 + ar) * DD + akg * 64;
        const uint32_t abase = (uint32_t)(ar * ARB + akg * 128);
#pragma unroll
        for (int i = 0; i < 8; i++) {
            float4 f0 = *(const float4*)(ap + i * 8);
            float4 f1 = *(const float4*)(ap + i * 8 + 4);
            float h0 = __bfloat162float(__float2bfloat16(f0.x));
            float h1 = __bfloat162float(__float2bfloat16(f0.y));
            float h2 = __bfloat162float(__float2bfloat16(f0.z));
            float h3 = __bfloat162float(__float2bfloat16(f0.w));
            float h4 = __bfloat162float(__float2bfloat16(f1.x));
            float h5 = __bfloat162float(__float2bfloat16(f1.y));
            float h6 = __bfloat162float(__float2bfloat16(f1.z));
            float h7 = __bfloat162float(__float2bfloat16(f1.w));
            uint4 hv, lv;
            hv.x = pack_bf2(h0, h1); hv.y = pack_bf2(h2, h3);
            hv.z = pack_bf2(h4, h5); hv.w = pack_bf2(h6, h7);
            lv.x = pack_bf2(f0.x - h0, f0.y - h1);
            lv.y = pack_bf2(f0.z - h2, f0.w - h3);
            lv.z = pack_bf2(f1.x - h4, f1.y - h5);
            lv.w = pack_bf2(f1.z - h6, f1.w - h7);
            *(uint4*)(smem + A_H + abase + i * 16) = hv;
            *(uint4*)(smem + A_L + abase + i * 16) = lv;
        }
    }

    // W cp.async assignment: thread -> (n row, hi/lo); 64B per thread/chunk
    const int wrow = tid & 255;
    const int whl  = tid >> 8;
    const __nv_bfloat16* wsrc = (whl ? g_WlT : g_WhT) + (size_t)wrow * DD;
    const uint32_t w_rel = (uint32_t)(W_BASE + (whl ? W_LOFF : 0) + wrow * WROWB);

    // chunk 0 in flight
#pragma unroll
    for (int q = 0; q < 4; q++)
        cpa16(sb + w_rel + q * 16, (const char*)wsrc + q * 16);
    CP_COMMIT();

    float c[4][4][4];
#pragma unroll
    for (int i = 0; i < 4; i++)
#pragma unroll
        for (int j = 0; j < 4; j++)
#pragma unroll
            for (int r = 0; r < 4; r++) c[i][j][r] = 0.f;

    // ldmatrix address components (chunk-invariant)
    const uint32_t a_ldm_rel = (uint32_t)((wg * 64 + (lane & 15)) * ARB + (lane >> 4) * 16);
    const int nofs  = (lane & 7) + ((lane >> 4) & 1) * 8;
    const int khalf = (lane >> 3) & 1;
    const uint32_t b_ldm_rel0 = (uint32_t)(W_BASE + (wn * 32 + nofs) * WROWB + khalf * 16);

    for (int cch = 0; cch < 8; cch++) {
        CP_WAIT0();
        __syncthreads();   // chunk cch visible to all; prev buffer free

        if (cch < 7) {     // prefetch next W chunk into the other stage
            const uint32_t ndst = sb + w_rel + ((cch + 1) & 1) * W_STAGE;
            const char* ws = (const char*)wsrc + (cch + 1) * (KC * 2);
#pragma unroll
            for (int q = 0; q < 4; q++)
                cpa16(ndst + q * 16, ws + q * 16);
            CP_COMMIT();
        }

        const uint32_t wbuf = (cch & 1) * W_STAGE;
        const uint32_t akb  = (uint32_t)(cch * 64);     // A k-byte offset
#pragma unroll
        for (int s = 0; s < 2; s++) {
            uint32_t bh[8], bl[8];
#pragma unroll
            for (int jp = 0; jp < 2; jp++) {
                uint32_t ba = sb + wbuf + b_ldm_rel0 + jp * 16 * WROWB + s * 32;
                ldm4(&bh[jp * 4], ba);
                ldm4(&bl[jp * 4], ba + W_LOFF);
            }
#pragma unroll
            for (int i = 0; i < 4; i++) {
                uint32_t ah[4], al[4];
                uint32_t aa = sb + A_H + a_ldm_rel + i * 16 * ARB + akb + s * 32;
                ldm4(ah, aa);
                ldm4(al, aa + (A_L - A_H));
#pragma unroll
                for (int j = 0; j < 4; j++) {
                    mma16816(c[i][j], ah, &bh[j * 2]);
                    mma16816(c[i][j], ah, &bl[j * 2]);
                    mma16816(c[i][j], al, &bh[j * 2]);
                }
            }
        }
    }

    // ---- epilogue: score[row] = sum_col tanh(C[row,col]) * v[col]
    const float* sv = (const float*)(smem + SV_OFF);
    float mv0[4], mv1[4];
#pragma unroll
    for (int j = 0; j < 4; j++) {
        int col = wn * 32 + j * 8 + (lane & 3) * 2;
        mv0[j] = sv[col];
        mv1[j] = sv[col + 1];
    }
    float* red = (float*)(smem + RED_OFF);
#pragma unroll
    for (int i = 0; i < 4; i++) {
#pragma unroll
        for (int rh = 0; rh < 2; rh++) {
            float p = 0.f;
#pragma unroll
            for (int j = 0; j < 4; j++) {
                p = fmaf(fast_tanh(c[i][j][rh * 2 + 0]), mv0[j], p);
                p = fmaf(fast_tanh(c[i][j][rh * 2 + 1]), mv1[j], p);
            }
            p += __shfl_xor_sync(0xffffffffu, p, 1);
            p += __shfl_xor_sync(0xffffffffu, p, 2);
            if ((lane & 3) == 0)
                red[(wg * 64 + i * 16 + rh * 8 + (lane >> 2)) * 8 + wn] = p;
        }
    }
    __syncthreads();
    if (tid < 128) {
        float s = 0.f;
#pragma unroll
        for (int w = 0; w < 8; w++) s += red[tid * 8 + w];
        g_scores[row0 + tid] = s;
    }
}

// ---------------- phase 2: softmax over T per batch -------------------------
__global__ void softmax_kernel(float* __restrict__ weights)
{
    const int b   = blockIdx.x;
    const int tid = threadIdx.x;
    const float* s = g_scores + (size_t)b * TT;
    __shared__ float red[256];

    float sc[16];
    float m = -INFINITY;
#pragma unroll
    for (int i = 0; i < 16; i++) {
        sc[i] = s[tid + i * 256];
        m = fmaxf(m, sc[i]);
    }
    red[tid] = m;
    __syncthreads();
    for (int st = 128; st > 0; st >>= 1) {
        if (tid < st) red[tid] = fmaxf(red[tid], red[tid + st]);
        __syncthreads();
    }
    m = red[0];
    __syncthreads();

    float sum = 0.f;
#pragma unroll
    for (int i = 0; i < 16; i++) {
        sc[i] = expf(sc[i] - m);
        sum += sc[i];
    }
    red[tid] = sum;
    __syncthreads();
    for (int st = 128; st > 0; st >>= 1) {
        if (tid < st) red[tid] += red[tid + st];
        __syncthreads();
    }
    const float inv = 1.f / red[0];
#pragma unroll
    for (int i = 0; i < 16; i++)
        weights[(size_t)b * TT + tid + i * 256] = sc[i] * inv;
}

// ---------------- phase 3: context, 2-stage (1024 blocks, deep MLP) --------
__global__ void __launch_bounds__(256)
ctx_part_kernel(const float* __restrict__ X, const float* __restrict__ w)
{
    const int b   = blockIdx.x;
    const int seg = blockIdx.y;                 // 0..15, 256 timesteps each
    const int q   = threadIdx.x & 63;           // float4 slot over d
    const int tr  = threadIdx.x >> 6;           // 0..3 t-lane
    const float* xb = X + ((size_t)b * TT + seg * 256) * DD + q * 4;
    const float* wb = w + (size_t)b * TT + seg * 256;

    float4 a0 = make_float4(0.f, 0.f, 0.f, 0.f);
    float4 a1 = make_float4(0.f, 0.f, 0.f, 0.f);
    for (int it = 0; it < 64; it += 8) {
#pragma unroll
        for (int u2 = 0; u2 < 8; u2++) {
            int t = (it + u2) * 4 + tr;
            float wt = wb[t];
            float4 xv = *(const float4*)(xb + (size_t)t * DD);
            if (u2 & 1) {
                a1.x = fmaf(wt, xv.x, a1.x); a1.y = fmaf(wt, xv.y, a1.y);
                a1.z = fmaf(wt, xv.z, a1.z); a1.w = fmaf(wt, xv.w, a1.w);
            } else {
                a0.x = fmaf(wt, xv.x, a0.x); a0.y = fmaf(wt, xv.y, a0.y);
                a0.z = fmaf(wt, xv.z, a0.z); a0.w = fmaf(wt, xv.w, a0.w);
            }
        }
    }
    float4 acc;
    acc.x = a0.x + a1.x; acc.y = a0.y + a1.y;
    acc.z = a0.z + a1.z; acc.w = a0.w + a1.w;

    __shared__ float4 red[256];
    red[threadIdx.x] = acc;
    __syncthreads();
    if (tr == 0) {
        float4 a = red[q], b4 = red[q + 64], c4 = red[q + 128], d4 = red[q + 192];
        float4 r;
        r.x = (a.x + b4.x) + (c4.x + d4.x);
        r.y = (a.y + b4.y) + (c4.y + d4.y);
        r.z = (a.z + b4.z) + (c4.z + d4.z);
        r.w = (a.w + b4.w) + (c4.w + d4.w);
        *(float4*)&g_cpart[((size_t)seg * BB + b) * DD + q * 4] = r;
    }
}

__global__ void ctx_final_kernel(float* __restrict__ ctx)
{
    const int b = blockIdx.x, d = threadIdx.x;
    float s = 0.f;
#pragma unroll
    for (int seg = 0; seg < 16; seg++)
        s += g_cpart[((size_t)seg * BB + b) * DD + d];
    ctx[(size_t)b * DD + d] = s;
}

// ---------------------------------------------------------------------------
extern "C" void kernel_launch(void* const* d_in, const int* in_sizes, int n_in,
                              void* d_out, int out_size)
{
    const float* X  = (const float*)d_in[0];
    const float* W1 = (const float*)d_in[1];
    const float* W2 = (const float*)d_in[2];
    const float* v  = (const float*)d_in[3];

    float* out     = (float*)d_out;
    float* ctx     = out;               // context_vector: B*D floats
    float* weights = out + BB * DD;     // attention_weights: B*T floats

    cudaFuncSetAttribute(score_mma_kernel,
                         cudaFuncAttributeMaxDynamicSharedMemorySize, SM_TOTAL);

    prep_w<<<256, 256>>>(W1, W2);
    score_mma_kernel<<<(BB * TT) / 128, 512, SM_TOTAL>>>(X, v);
    softmax_kernel<<<BB, 256>>>(weights);
    ctx_part_kernel<<<dim3(BB, 16), 256>>>(X, weights);
    ctx_final_kernel<<<BB, 256>>>(ctx);
}

// round 6
// speedup vs baseline: 1.7652x; 1.7652x over previous
#include <cuda_runtime.h>
#include <cuda_fp16.h>
#include <math.h>
#include <stdint.h>

#define BB 64
#define TT 4096
#define DD 256
#define UU 256

// ---------------- device-global scratch (allocation-free rule) -------------
__device__ float g_scores[BB * TT];
__device__ float g_cpart[16 * BB * DD];
__device__ __align__(16) __half g_WhT[UU * DD];   // (W1+W2)^T hi fp16, [n][k]
__device__ __align__(16) __half g_WlT[UU * DD];   // (W1+W2)^T lo fp16, [n][k]

// ---------------- smem layout for score kernel -----------------------------
#define KC     32            // k per chunk
#define ROWB   80            // padded row: 32 fp16 = 64B data + 16B pad
#define A_OFF  0             // X fp16: 128 rows * 80B = 10240
#define W_H    10240         // W hi: 256 rows * 80B = 20480
#define W_L    30720         // W lo: 20480
#define BUFSZ  51200
#define RED_OFF 102400       // 128 rows * 8 warps * 4B = 4KB
#define SV_OFF  106496       // 256 floats
#define SM_TOTAL 107520

// ---------------- PTX helpers (plain sm_103-legal: no 'a' features) --------
__device__ __forceinline__ uint32_t smem_u32(const void* p) {
    uint32_t a;
    asm("{ .reg .u64 t; cvta.to.shared.u64 t, %1; cvt.u32.u64 %0, t; }"
        : "=r"(a) : "l"(p));
    return a;
}
__device__ __forceinline__ void ldm4(uint32_t* r, uint32_t addr) {
    asm volatile("ldmatrix.sync.aligned.m8n8.x4.shared.b16 {%0,%1,%2,%3}, [%4];"
                 : "=r"(r[0]), "=r"(r[1]), "=r"(r[2]), "=r"(r[3]) : "r"(addr));
}
__device__ __forceinline__ void mma16816(float* c, const uint32_t* a, const uint32_t* b) {
    asm volatile(
        "mma.sync.aligned.m16n8k16.row.col.f32.f16.f16.f32 "
        "{%0,%1,%2,%3},{%4,%5,%6,%7},{%8,%9},{%0,%1,%2,%3};"
        : "+f"(c[0]), "+f"(c[1]), "+f"(c[2]), "+f"(c[3])
        : "r"(a[0]), "r"(a[1]), "r"(a[2]), "r"(a[3]), "r"(b[0]), "r"(b[1]));
}
__device__ __forceinline__ void cpa16(uint32_t dst, const void* src) {
    asm volatile("cp.async.ca.shared.global [%0], [%1], 16;" :: "r"(dst), "l"(src));
}
#define CP_COMMIT() asm volatile("cp.async.commit_group;" ::: "memory")
#define CP_WAIT0()  asm volatile("cp.async.wait_group 0;" ::: "memory")

__device__ __forceinline__ uint32_t pack_h2(float a, float b) {
    __half2 t = __floats2half2_rn(a, b);
    return *(uint32_t*)&t;
}
__device__ __forceinline__ float fast_tanh(float q) {
    float e = __expf(2.f * q);
    return 1.f - __fdividef(2.f, e + 1.f);   // exact limits at +/-inf
}

// ---------------- phase 0: fuse + split + transpose weights ----------------
__global__ void prep_w(const float* __restrict__ W1, const float* __restrict__ W2)
{
    int idx = blockIdx.x * 256 + threadIdx.x;   // idx = k*256 + u
    int k = idx >> 8, u = idx & 255;
    float w = W1[idx] + W2[idx];
    __half h = __float2half_rn(w);
    __half l = __float2half_rn(w - __half2float(h));
    g_WhT[u * DD + k] = h;
    g_WlT[u * DD + k] = l;
}

// ---------------- phase 1: HMMA GEMM + tanh/v epilogue ---------------------
// 512 threads, tile M=128 x N=256, K chunks of 32 (double-buffered).
// X as single fp16; W = fp16 hi+lo. 2 MMA products per (i,j) pair.
// 16 warps: wg=wid>>3 picks row-half (64 rows), wn=wid&7 picks 32-col slice.
__global__ void __launch_bounds__(512, 1)
score_mma_kernel(const float* __restrict__ X, const float* __restrict__ v)
{
    extern __shared__ char smem[];
    const uint32_t sb = smem_u32(smem);
    const int tid  = threadIdx.x;
    const int wid  = tid >> 5, lane = tid & 31;
    const int wg   = wid >> 3, wn = wid & 7;
    const long row0 = (long)blockIdx.x * 128;

    if (tid < 256) ((float*)(smem + SV_OFF))[tid] = v[tid];

    // A (X) prefetch assignment: thread -> (row, 8-k group)
    const int ar  = tid >> 2;                 // 0..127
    const int akg = tid & 3;                  // 0..3
    const float* aptr = X + (row0 + ar) * DD + akg * 8;
    const uint32_t a_rel = (uint32_t)(A_OFF + ar * ROWB + akg * 16);

    // W cp.async assignment: thread -> (n row, hi/lo); one 64B row per thread
    const int wrow = tid & 255;
    const int whl  = tid >> 8;                // 0:hi 1:lo
    const __half* wsrc = (whl ? g_WlT : g_WhT) + (size_t)wrow * DD;
    const uint32_t w_rel = (uint32_t)((whl ? W_L : W_H) + wrow * ROWB);

    float c[4][4][4];
#pragma unroll
    for (int i = 0; i < 4; i++)
#pragma unroll
        for (int j = 0; j < 4; j++)
#pragma unroll
            for (int r = 0; r < 4; r++) c[i][j][r] = 0.f;

    // ldmatrix address components (chunk-invariant parts)
    const uint32_t a_ldm_rel = (uint32_t)(A_OFF + (wg * 64 + (lane & 15)) * ROWB + (lane >> 4) * 16);
    const int nofs  = (lane & 7) + ((lane >> 4) & 1) * 8;
    const int khalf = (lane >> 3) & 1;
    const uint32_t b_ldm_rel0 = (uint32_t)(W_H + (wn * 32 + nofs) * ROWB + khalf * 16);

    // ---- prologue: chunk 0 in flight
    float4 f0 = *(const float4*)(aptr);
    float4 f1 = *(const float4*)(aptr + 4);
#pragma unroll
    for (int q = 0; q < 4; q++)
        cpa16(sb + w_rel + q * 16, (const char*)(wsrc) + q * 16);
    CP_COMMIT();

    for (int cch = 0; cch < 8; cch++) {
        const uint32_t buf = (cch & 1) * BUFSZ;
        // store A chunk as fp16 (single plane)
        {
            uint4 hv;
            hv.x = pack_h2(f0.x, f0.y);
            hv.y = pack_h2(f0.z, f0.w);
            hv.z = pack_h2(f1.x, f1.y);
            hv.w = pack_h2(f1.z, f1.w);
            *(uint4*)(smem + buf + a_rel) = hv;
        }
        CP_WAIT0();
        __syncthreads();

        if (cch < 7) {  // prefetch next chunk
            const float* ap = aptr + (cch + 1) * KC;
            f0 = *(const float4*)(ap);
            f1 = *(const float4*)(ap + 4);
            const uint32_t nbuf = ((cch + 1) & 1) * BUFSZ;
            const char* ws = (const char*)wsrc + (cch + 1) * (KC * 2);
#pragma unroll
            for (int q = 0; q < 4; q++)
                cpa16(sb + nbuf + w_rel + q * 16, ws + q * 16);
            CP_COMMIT();
        }

        // compute: 2 k16-steps on this chunk
#pragma unroll
        for (int s = 0; s < 2; s++) {
            uint32_t bh[8], bl[8];
#pragma unroll
            for (int jp = 0; jp < 2; jp++) {
                uint32_t ba = sb + buf + b_ldm_rel0 + jp * 16 * ROWB + s * 32;
                ldm4(&bh[jp * 4], ba);
                ldm4(&bl[jp * 4], ba + (W_L - W_H));
            }
#pragma unroll
            for (int i = 0; i < 4; i++) {
                uint32_t ah[4];
                uint32_t aa = sb + buf + a_ldm_rel + i * 16 * ROWB + s * 32;
                ldm4(ah, aa);
#pragma unroll
                for (int j = 0; j < 4; j++) {
                    mma16816(c[i][j], ah, &bh[j * 2]);
                    mma16816(c[i][j], ah, &bl[j * 2]);
                }
            }
        }
    }

    // ---- epilogue: score[row] = sum_col tanh(C[row,col]) * v[col]
    const float* sv = (const float*)(smem + SV_OFF);
    float mv0[4], mv1[4];
#pragma unroll
    for (int j = 0; j < 4; j++) {
        int col = wn * 32 + j * 8 + (lane & 3) * 2;
        mv0[j] = sv[col];
        mv1[j] = sv[col + 1];
    }
    float* red = (float*)(smem + RED_OFF);
#pragma unroll
    for (int i = 0; i < 4; i++) {
#pragma unroll
        for (int rh = 0; rh < 2; rh++) {
            float p = 0.f;
#pragma unroll
            for (int j = 0; j < 4; j++) {
                p = fmaf(fast_tanh(c[i][j][rh * 2 + 0]), mv0[j], p);
                p = fmaf(fast_tanh(c[i][j][rh * 2 + 1]), mv1[j], p);
            }
            p += __shfl_xor_sync(0xffffffffu, p, 1);
            p += __shfl_xor_sync(0xffffffffu, p, 2);
            if ((lane & 3) == 0)
                red[(wg * 64 + i * 16 + rh * 8 + (lane >> 2)) * 8 + wn] = p;
        }
    }
    __syncthreads();
    if (tid < 128) {
        float s = 0.f;
#pragma unroll
        for (int w = 0; w < 8; w++) s += red[tid * 8 + w];
        g_scores[row0 + tid] = s;
    }
}

// ---------------- phase 2: softmax over T per batch -------------------------
__global__ void softmax_kernel(float* __restrict__ weights)
{
    const int b   = blockIdx.x;
    const int tid = threadIdx.x;
    const float* s = g_scores + (size_t)b * TT;
    __shared__ float red[256];

    float sc[16];
    float m = -INFINITY;
#pragma unroll
    for (int i = 0; i < 16; i++) {
        sc[i] = s[tid + i * 256];
        m = fmaxf(m, sc[i]);
    }
    red[tid] = m;
    __syncthreads();
    for (int st = 128; st > 0; st >>= 1) {
        if (tid < st) red[tid] = fmaxf(red[tid], red[tid + st]);
        __syncthreads();
    }
    m = red[0];
    __syncthreads();

    float sum = 0.f;
#pragma unroll
    for (int i = 0; i < 16; i++) {
        sc[i] = expf(sc[i] - m);
        sum += sc[i];
    }
    red[tid] = sum;
    __syncthreads();
    for (int st = 128; st > 0; st >>= 1) {
        if (tid < st) red[tid] += red[tid + st];
        __syncthreads();
    }
    const float inv = 1.f / red[0];
#pragma unroll
    for (int i = 0; i < 16; i++)
        weights[(size_t)b * TT + tid + i * 256] = sc[i] * inv;
}

// ---------------- phase 3: context, 2-stage (1024 blocks, float4) ----------
__global__ void __launch_bounds__(256)
ctx_part_kernel(const float* __restrict__ X, const float* __restrict__ w)
{
    const int b   = blockIdx.x;
    const int seg = blockIdx.y;                 // 0..15, 256 timesteps each
    const int q   = threadIdx.x & 63;           // float4 slot over d
    const int tr  = threadIdx.x >> 6;           // 0..3 t-lane
    const float* xb = X + ((size_t)b * TT + seg * 256) * DD + q * 4;
    const float* wb = w + (size_t)b * TT + seg * 256;

    float4 acc = make_float4(0.f, 0.f, 0.f, 0.f);
    for (int it = 0; it < 64; it += 4) {
#pragma unroll
        for (int u2 = 0; u2 < 4; u2++) {
            int t = (it + u2) * 4 + tr;
            float wt = wb[t];
            float4 xv = *(const float4*)(xb + (size_t)t * DD);
            acc.x = fmaf(wt, xv.x, acc.x);
            acc.y = fmaf(wt, xv.y, acc.y);
            acc.z = fmaf(wt, xv.z, acc.z);
            acc.w = fmaf(wt, xv.w, acc.w);
        }
    }

    __shared__ float4 red[256];
    red[threadIdx.x] = acc;
    __syncthreads();
    if (tr == 0) {
        float4 a = red[q], b4 = red[q + 64], c4 = red[q + 128], d4 = red[q + 192];
        float4 r;
        r.x = (a.x + b4.x) + (c4.x + d4.x);
        r.y = (a.y + b4.y) + (c4.y + d4.y);
        r.z = (a.z + b4.z) + (c4.z + d4.z);
        r.w = (a.w + b4.w) + (c4.w + d4.w);
        *(float4*)&g_cpart[((size_t)seg * BB + b) * DD + q * 4] = r;
    }
}

__global__ void ctx_final_kernel(float* __restrict__ ctx)
{
    const int b = blockIdx.x, d = threadIdx.x;
    float s = 0.f;
#pragma unroll
    for (int seg = 0; seg < 16; seg++)
        s += g_cpart[((size_t)seg * BB + b) * DD + d];
    ctx[(size_t)b * DD + d] = s;
}

// ---------------------------------------------------------------------------
extern "C" void kernel_launch(void* const* d_in, const int* in_sizes, int n_in,
                              void* d_out, int out_size)
{
    const float* X  = (const float*)d_in[0];
    const float* W1 = (const float*)d_in[1];
    const float* W2 = (const float*)d_in[2];
    const float* v  = (const float*)d_in[3];

    float* out     = (float*)d_out;
    float* ctx     = out;               // context_vector: B*D floats
    float* weights = out + BB * DD;     // attention_weights: B*T floats

    cudaFuncSetAttribute(score_mma_kernel,
                         cudaFuncAttributeMaxDynamicSharedMemorySize, SM_TOTAL);

    prep_w<<<256, 256>>>(W1, W2);
    score_mma_kernel<<<(BB * TT) / 128, 512, SM_TOTAL>>>(X, v);
    softmax_kernel<<<BB, 256>>>(weights);
    ctx_part_kernel<<<dim3(BB, 16), 256>>>(X, weights);
    ctx_final_kernel<<<BB, 256>>>(ctx);
}

// round 7
// speedup vs baseline: 2.2697x; 1.2858x over previous
#include <cuda_runtime.h>
#include <cuda_fp16.h>
#include <math.h>
#include <stdint.h>

#define BB 64
#define TT 4096
#define DD 256
#define UU 256

// ---------------- device-global scratch (allocation-free rule) -------------
__device__ float g_scores[BB * TT];
__device__ float g_cpart[16 * BB * DD];
__device__ __align__(16) __half g_WT[UU * DD];   // (W1+W2)^T fp16, [n][k]

// ---------------- smem layout for score kernel -----------------------------
#define KC     64            // k per chunk
#define ROWB   144           // padded row: 64 fp16 = 128B data + 16B pad
#define A_OFF  0             // X fp16: 128 rows * 144B = 18432
#define W_OFF  18432         // W fp16: 256 rows * 144B = 36864
#define BUFSZ  55296
#define RED_OFF 110592       // 128 rows * 8 warps * 4B = 4KB
#define SV_OFF  114688       // 256 floats
#define SM_TOTAL 115712

// ---------------- PTX helpers (plain sm_103-legal: no 'a' features) --------
__device__ __forceinline__ uint32_t smem_u32(const void* p) {
    uint32_t a;
    asm("{ .reg .u64 t; cvta.to.shared.u64 t, %1; cvt.u32.u64 %0, t; }"
        : "=r"(a) : "l"(p));
    return a;
}
__device__ __forceinline__ void ldm4(uint32_t* r, uint32_t addr) {
    asm volatile("ldmatrix.sync.aligned.m8n8.x4.shared.b16 {%0,%1,%2,%3}, [%4];"
                 : "=r"(r[0]), "=r"(r[1]), "=r"(r[2]), "=r"(r[3]) : "r"(addr));
}
__device__ __forceinline__ void mma16816(float* c, const uint32_t* a, const uint32_t* b) {
    asm volatile(
        "mma.sync.aligned.m16n8k16.row.col.f32.f16.f16.f32 "
        "{%0,%1,%2,%3},{%4,%5,%6,%7},{%8,%9},{%0,%1,%2,%3};"
        : "+f"(c[0]), "+f"(c[1]), "+f"(c[2]), "+f"(c[3])
        : "r"(a[0]), "r"(a[1]), "r"(a[2]), "r"(a[3]), "r"(b[0]), "r"(b[1]));
}
__device__ __forceinline__ void cpa16(uint32_t dst, const void* src) {
    asm volatile("cp.async.ca.shared.global [%0], [%1], 16;" :: "r"(dst), "l"(src));
}
#define CP_COMMIT() asm volatile("cp.async.commit_group;" ::: "memory")
#define CP_WAIT0()  asm volatile("cp.async.wait_group 0;" ::: "memory")

__device__ __forceinline__ uint32_t pack_h2(float a, float b) {
    __half2 t = __floats2half2_rn(a, b);
    return *(uint32_t*)&t;
}
__device__ __forceinline__ float fast_tanh(float q) {
    float e = __expf(2.f * q);
    return 1.f - __fdividef(2.f, e + 1.f);   // exact limits at +/-inf
}

// ---------------- phase 0: fuse + transpose weights (fp16) -----------------
__global__ void prep_w(const float* __restrict__ W1, const float* __restrict__ W2)
{
    int idx = blockIdx.x * 256 + threadIdx.x;   // idx = k*256 + u
    int k = idx >> 8, u = idx & 255;
    g_WT[u * DD + k] = __float2half_rn(W1[idx] + W2[idx]);
}

// ---------------- phase 1: HMMA GEMM + tanh/v epilogue ---------------------
// 512 threads, tile M=128 x N=256, K chunks of 64 (double-buffered).
// X and W as single fp16 planes; one MMA product per (i,j,s).
// 16 warps: wg=wid>>3 picks row-half (64 rows), wn=wid&7 picks 32-col slice.
__global__ void __launch_bounds__(512, 1)
score_mma_kernel(const float* __restrict__ X, const float* __restrict__ v)
{
    extern __shared__ char smem[];
    const uint32_t sb = smem_u32(smem);
    const int tid  = threadIdx.x;
    const int wid  = tid >> 5, lane = tid & 31;
    const int wg   = wid >> 3, wn = wid & 7;
    const long row0 = (long)blockIdx.x * 128;

    if (tid < 256) ((float*)(smem + SV_OFF))[tid] = v[tid];

    // A (X) prefetch assignment: thread -> (row, 16-float segment of chunk)
    const int ar  = tid >> 2;                 // 0..127
    const int akg = tid & 3;                  // 0..3
    const float* aptr = X + (row0 + ar) * DD + akg * 16;
    const uint32_t a_rel = (uint32_t)(A_OFF + ar * ROWB + akg * 32);

    // W cp.async assignment: thread -> (n row, 64B half-row)
    const int wrow = tid & 255;
    const int wseg = tid >> 8;                // 0..1
    const __half* wsrc = g_WT + (size_t)wrow * DD + wseg * 32;
    const uint32_t w_rel = (uint32_t)(W_OFF + wrow * ROWB + wseg * 64);

    float c[4][4][4];
#pragma unroll
    for (int i = 0; i < 4; i++)
#pragma unroll
        for (int j = 0; j < 4; j++)
#pragma unroll
            for (int r = 0; r < 4; r++) c[i][j][r] = 0.f;

    // ldmatrix address components (chunk-invariant parts)
    const uint32_t a_ldm_rel = (uint32_t)(A_OFF + (wg * 64 + (lane & 15)) * ROWB + (lane >> 4) * 16);
    const int nofs  = (lane & 7) + ((lane >> 4) & 1) * 8;
    const int khalf = (lane >> 3) & 1;
    const uint32_t b_ldm_rel0 = (uint32_t)(W_OFF + (wn * 32 + nofs) * ROWB + khalf * 16);

    // ---- prologue: chunk 0 in flight
    float4 f[4];
#pragma unroll
    for (int q = 0; q < 4; q++) f[q] = *(const float4*)(aptr + q * 4);
#pragma unroll
    for (int q = 0; q < 4; q++)
        cpa16(sb + w_rel + q * 16, (const char*)wsrc + q * 16);
    CP_COMMIT();

    for (int cch = 0; cch < 4; cch++) {
        const uint32_t buf = (cch & 1) * BUFSZ;
        // store A chunk as fp16
        {
            uint4 h0, h1;
            h0.x = pack_h2(f[0].x, f[0].y); h0.y = pack_h2(f[0].z, f[0].w);
            h0.z = pack_h2(f[1].x, f[1].y); h0.w = pack_h2(f[1].z, f[1].w);
            h1.x = pack_h2(f[2].x, f[2].y); h1.y = pack_h2(f[2].z, f[2].w);
            h1.z = pack_h2(f[3].x, f[3].y); h1.w = pack_h2(f[3].z, f[3].w);
            *(uint4*)(smem + buf + a_rel)      = h0;
            *(uint4*)(smem + buf + a_rel + 16) = h1;
        }
        CP_WAIT0();
        __syncthreads();

        if (cch < 3) {  // prefetch next chunk
            const float* ap = aptr + (cch + 1) * KC;
#pragma unroll
            for (int q = 0; q < 4; q++) f[q] = *(const float4*)(ap + q * 4);
            const uint32_t nbuf = ((cch + 1) & 1) * BUFSZ;
            const char* ws = (const char*)wsrc + (cch + 1) * (KC * 2);
#pragma unroll
            for (int q = 0; q < 4; q++)
                cpa16(sb + nbuf + w_rel + q * 16, ws + q * 16);
            CP_COMMIT();
        }

        // compute: 4 k16-steps on this chunk
#pragma unroll
        for (int s = 0; s < 4; s++) {
            uint32_t bh[8];
#pragma unroll
            for (int jp = 0; jp < 2; jp++) {
                uint32_t ba = sb + buf + b_ldm_rel0 + jp * 16 * ROWB + s * 32;
                ldm4(&bh[jp * 4], ba);
            }
#pragma unroll
            for (int i = 0; i < 4; i++) {
                uint32_t ah[4];
                uint32_t aa = sb + buf + a_ldm_rel + i * 16 * ROWB + s * 32;
                ldm4(ah, aa);
#pragma unroll
                for (int j = 0; j < 4; j++)
                    mma16816(c[i][j], ah, &bh[j * 2]);
            }
        }
    }

    // ---- epilogue: score[row] = sum_col tanh(C[row,col]) * v[col]
    const float* sv = (const float*)(smem + SV_OFF);
    float mv0[4], mv1[4];
#pragma unroll
    for (int j = 0; j < 4; j++) {
        int col = wn * 32 + j * 8 + (lane & 3) * 2;
        mv0[j] = sv[col];
        mv1[j] = sv[col + 1];
    }
    float* red = (float*)(smem + RED_OFF);
#pragma unroll
    for (int i = 0; i < 4; i++) {
#pragma unroll
        for (int rh = 0; rh < 2; rh++) {
            float p = 0.f;
#pragma unroll
            for (int j = 0; j < 4; j++) {
                p = fmaf(fast_tanh(c[i][j][rh * 2 + 0]), mv0[j], p);
                p = fmaf(fast_tanh(c[i][j][rh * 2 + 1]), mv1[j], p);
            }
            p += __shfl_xor_sync(0xffffffffu, p, 1);
            p += __shfl_xor_sync(0xffffffffu, p, 2);
            if ((lane & 3) == 0)
                red[(wg * 64 + i * 16 + rh * 8 + (lane >> 2)) * 8 + wn] = p;
        }
    }
    __syncthreads();
    if (tid < 128) {
        float s = 0.f;
#pragma unroll
        for (int w = 0; w < 8; w++) s += red[tid * 8 + w];
        g_scores[row0 + tid] = s;
    }
}

// ---------------- phase 2: softmax over T per batch -------------------------
__global__ void softmax_kernel(float* __restrict__ weights)
{
    const int b   = blockIdx.x;
    const int tid = threadIdx.x;
    const float* s = g_scores + (size_t)b * TT;
    __shared__ float red[256];

    float sc[16];
    float m = -INFINITY;
#pragma unroll
    for (int i = 0; i < 16; i++) {
        sc[i] = s[tid + i * 256];
        m = fmaxf(m, sc[i]);
    }
    red[tid] = m;
    __syncthreads();
    for (int st = 128; st > 0; st >>= 1) {
        if (tid < st) red[tid] = fmaxf(red[tid], red[tid + st]);
        __syncthreads();
    }
    m = red[0];
    __syncthreads();

    float sum = 0.f;
#pragma unroll
    for (int i = 0; i < 16; i++) {
        sc[i] = expf(sc[i] - m);
        sum += sc[i];
    }
    red[tid] = sum;
    __syncthreads();
    for (int st = 128; st > 0; st >>= 1) {
        if (tid < st) red[tid] += red[tid + st];
        __syncthreads();
    }
    const float inv = 1.f / red[0];
#pragma unroll
    for (int i = 0; i < 16; i++)
        weights[(size_t)b * TT + tid + i * 256] = sc[i] * inv;
}

// ---------------- phase 3: context, 2-stage (1024 blocks, float4) ----------
__global__ void __launch_bounds__(256)
ctx_part_kernel(const float* __restrict__ X, const float* __restrict__ w)
{
    const int b   = blockIdx.x;
    const int seg = blockIdx.y;                 // 0..15, 256 timesteps each
    const int q   = threadIdx.x & 63;           // float4 slot over d
    const int tr  = threadIdx.x >> 6;           // 0..3 t-lane
    const float* xb = X + ((size_t)b * TT + seg * 256) * DD + q * 4;
    const float* wb = w + (size_t)b * TT + seg * 256;

    float4 acc = make_float4(0.f, 0.f, 0.f, 0.f);
    for (int it = 0; it < 64; it += 4) {
#pragma unroll
        for (int u2 = 0; u2 < 4; u2++) {
            int t = (it + u2) * 4 + tr;
            float wt = wb[t];
            float4 xv = *(const float4*)(xb + (size_t)t * DD);
            acc.x = fmaf(wt, xv.x, acc.x);
            acc.y = fmaf(wt, xv.y, acc.y);
            acc.z = fmaf(wt, xv.z, acc.z);
            acc.w = fmaf(wt, xv.w, acc.w);
        }
    }

    __shared__ float4 red[256];
    red[threadIdx.x] = acc;
    __syncthreads();
    if (tr == 0) {
        float4 a = red[q], b4 = red[q + 64], c4 = red[q + 128], d4 = red[q + 192];
        float4 r;
        r.x = (a.x + b4.x) + (c4.x + d4.x);
        r.y = (a.y + b4.y) + (c4.y + d4.y);
        r.z = (a.z + b4.z) + (c4.z + d4.z);
        r.w = (a.w + b4.w) + (c4.w + d4.w);
        *(float4*)&g_cpart[((size_t)seg * BB + b) * DD + q * 4] = r;
    }
}

__global__ void ctx_final_kernel(float* __restrict__ ctx)
{
    const int b = blockIdx.x, d = threadIdx.x;
    float s = 0.f;
#pragma unroll
    for (int seg = 0; seg < 16; seg++)
        s += g_cpart[((size_t)seg * BB + b) * DD + d];
    ctx[(size_t)b * DD + d] = s;
}

// ---------------------------------------------------------------------------
extern "C" void kernel_launch(void* const* d_in, const int* in_sizes, int n_in,
                              void* d_out, int out_size)
{
    const float* X  = (const float*)d_in[0];
    const float* W1 = (const float*)d_in[1];
    const float* W2 = (const float*)d_in[2];
    const float* v  = (const float*)d_in[3];

    float* out     = (float*)d_out;
    float* ctx     = out;               // context_vector: B*D floats
    float* weights = out + BB * DD;     // attention_weights: B*T floats

    cudaFuncSetAttribute(score_mma_kernel,
                         cudaFuncAttributeMaxDynamicSharedMemorySize, SM_TOTAL);

    prep_w<<<256, 256>>>(W1, W2);
    score_mma_kernel<<<(BB * TT) / 128, 512, SM_TOTAL>>>(X, v);
    softmax_kernel<<<BB, 256>>>(weights);
    ctx_part_kernel<<<dim3(BB, 16), 256>>>(X, weights);
    ctx_final_kernel<<<BB, 256>>>(ctx);
}

// round 8
// speedup vs baseline: 3.5504x; 1.5642x over previous
#include <cuda_runtime.h>
#include <cuda_fp16.h>
#include <math.h>
#include <stdint.h>

#define BB 64
#define TT 4096
#define DD 256
#define UU 256
#define NTILES 2048          // (BB*TT)/128
#define NSM 152

// ---------------- device-global scratch (allocation-free rule) -------------
__device__ float g_scores[BB * TT];
__device__ float g_cpart[16 * BB * DD];
__device__ __align__(16) __half g_WT[UU * DD];   // (W1+W2)^T fp16, [n][k]

// ---------------- smem layout for score kernel -----------------------------
#define KC      64           // k per A chunk
#define WROWB   528          // W row: 512B data + 16B pad (528/4 mod 32 = 4 -> conflict-free)
#define AROWB   144          // A row: 128B data + 16B pad
#define W_OFF   0            // 256 rows * 528B = 135168
#define A_OFF   135168       // 2 stages * 128 rows * 144B = 36864
#define ABUF    18432
#define RED_OFF 172032       // 128 rows * 8 warps * 4B = 4096
#define SV_OFF  176128       // 256 floats
#define SM_TOTAL 177152

// ---------------- PTX helpers (plain sm_103-legal: no 'a' features) --------
__device__ __forceinline__ uint32_t smem_u32(const void* p) {
    uint32_t a;
    asm("{ .reg .u64 t; cvta.to.shared.u64 t, %1; cvt.u32.u64 %0, t; }"
        : "=r"(a) : "l"(p));
    return a;
}
__device__ __forceinline__ void ldm4(uint32_t* r, uint32_t addr) {
    asm volatile("ldmatrix.sync.aligned.m8n8.x4.shared.b16 {%0,%1,%2,%3}, [%4];"
                 : "=r"(r[0]), "=r"(r[1]), "=r"(r[2]), "=r"(r[3]) : "r"(addr));
}
__device__ __forceinline__ void mma16816(float* c, const uint32_t* a, const uint32_t* b) {
    asm volatile(
        "mma.sync.aligned.m16n8k16.row.col.f32.f16.f16.f32 "
        "{%0,%1,%2,%3},{%4,%5,%6,%7},{%8,%9},{%0,%1,%2,%3};"
        : "+f"(c[0]), "+f"(c[1]), "+f"(c[2]), "+f"(c[3])
        : "r"(a[0]), "r"(a[1]), "r"(a[2]), "r"(a[3]), "r"(b[0]), "r"(b[1]));
}
__device__ __forceinline__ void cpa16(uint32_t dst, const void* src) {
    asm volatile("cp.async.ca.shared.global [%0], [%1], 16;" :: "r"(dst), "l"(src));
}
#define CP_COMMIT() asm volatile("cp.async.commit_group;" ::: "memory")
#define CP_WAIT0()  asm volatile("cp.async.wait_group 0;" ::: "memory")

__device__ __forceinline__ uint32_t pack_h2(float a, float b) {
    __half2 t = __floats2half2_rn(a, b);
    return *(uint32_t*)&t;
}
__device__ __forceinline__ float fast_tanh(float q) {
    float e = __expf(2.f * q);
    return 1.f - __fdividef(2.f, e + 1.f);   // exact limits at +/-inf
}

// ---------------- phase 0: fuse + transpose weights (fp16) -----------------
__global__ void prep_w(const float* __restrict__ W1, const float* __restrict__ W2)
{
    int idx = blockIdx.x * 256 + threadIdx.x;   // idx = k*256 + u
    int k = idx >> 8, u = idx & 255;
    g_WT[u * DD + k] = __float2half_rn(W1[idx] + W2[idx]);
}

// ---------------- phase 1: persistent HMMA GEMM + tanh/v epilogue ----------
// 152 persistent CTAs x 512 threads. W (256x256 fp16) resident in smem.
// Per tile (128 rows): A restaged in 64-k chunks, double-buffered.
__global__ void __launch_bounds__(512, 1)
score_mma_kernel(const float* __restrict__ X, const float* __restrict__ v)
{
    extern __shared__ char smem[];
    const uint32_t sb = smem_u32(smem);
    const int tid  = threadIdx.x;
    const int wid  = tid >> 5, lane = tid & 31;
    const int wg   = wid >> 3, wn = wid & 7;

    // ---- prologue: W resident load (once) + v
    {
        // 8192 16B-units: unit u -> row u>>5, 16B-col u&31
#pragma unroll
        for (int i = 0; i < 16; i++) {
            int u = tid + i * 512;
            int row = u >> 5, c16 = u & 31;
            cpa16(sb + W_OFF + row * WROWB + c16 * 16,
                  (const char*)(g_WT + (size_t)row * DD) + c16 * 16);
        }
        CP_COMMIT();
    }
    if (tid < 256) ((float*)(smem + SV_OFF))[tid] = v[tid];

    // A assignment: thread -> (row, 16-float segment of chunk)
    const int ar  = tid >> 2;
    const int akg = tid & 3;
    const uint32_t a_rel = (uint32_t)(ar * AROWB + akg * 32);

    // ldmatrix address components
    const uint32_t a_ldm_rel = (uint32_t)(A_OFF + (wg * 64 + (lane & 15)) * AROWB + (lane >> 4) * 16);
    const int nofs  = (lane & 7) + ((lane >> 4) & 1) * 8;
    const int khalf = (lane >> 3) & 1;
    const uint32_t b_ldm_rel0 = (uint32_t)(W_OFF + (wn * 32 + nofs) * WROWB + khalf * 16);

    const float* sv = (const float*)(smem + SV_OFF);
    float* red = (float*)(smem + RED_OFF);

    float c[4][4][4];
#pragma unroll
    for (int i = 0; i < 4; i++)
#pragma unroll
        for (int j = 0; j < 4; j++)
#pragma unroll
            for (int r = 0; r < 4; r++) c[i][j][r] = 0.f;

    int tile  = blockIdx.x;
    int chunk = 0;
    int par   = 0;

    // first A chunk into registers
    float4 f[4];
    {
        const float* ap = X + ((size_t)tile * 128 + ar) * DD + akg * 16;
#pragma unroll
        for (int q = 0; q < 4; q++) f[q] = *(const float4*)(ap + q * 4);
    }
    CP_WAIT0();        // W resident ready (sync below publishes it)

    while (tile < NTILES) {
        // 1. stage A chunk into buffer 'par'
        {
            const uint32_t dst = sb + A_OFF + (uint32_t)par * ABUF + a_rel;
            uint4 h0, h1;
            h0.x = pack_h2(f[0].x, f[0].y); h0.y = pack_h2(f[0].z, f[0].w);
            h0.z = pack_h2(f[1].x, f[1].y); h0.w = pack_h2(f[1].z, f[1].w);
            h1.x = pack_h2(f[2].x, f[2].y); h1.y = pack_h2(f[2].z, f[2].w);
            h1.z = pack_h2(f[3].x, f[3].y); h1.w = pack_h2(f[3].z, f[3].w);
            *(uint4*)(smem + (dst - sb))      = h0;   // keep simple generic smem stores
            *(uint4*)(smem + (dst - sb) + 16) = h1;
        }
        __syncthreads();

        // 2. prefetch next (tile, chunk) A into registers
        int ntile = tile, nchunk = chunk + 1;
        if (nchunk == 4) { nchunk = 0; ntile = tile + NSM; }
        if (ntile < NTILES) {
            const float* ap = X + ((size_t)ntile * 128 + ar) * DD + nchunk * KC + akg * 16;
#pragma unroll
            for (int q = 0; q < 4; q++) f[q] = *(const float4*)(ap + q * 4);
        }

        // 3. compute 4 k16-steps on this chunk
        const uint32_t abuf = sb + A_OFF + (uint32_t)par * ABUF;
        const uint32_t wkb  = (uint32_t)(chunk * 128);
#pragma unroll
        for (int s = 0; s < 4; s++) {
            uint32_t bh[8];
#pragma unroll
            for (int jp = 0; jp < 2; jp++) {
                uint32_t ba = sb + b_ldm_rel0 + jp * 16 * WROWB + wkb + s * 32;
                ldm4(&bh[jp * 4], ba);
            }
#pragma unroll
            for (int i = 0; i < 4; i++) {
                uint32_t ah[4];
                uint32_t aa = abuf + (a_ldm_rel - A_OFF) + i * 16 * AROWB + s * 32;
                ldm4(ah, aa);
#pragma unroll
                for (int j = 0; j < 4; j++)
                    mma16816(c[i][j], ah, &bh[j * 2]);
            }
        }

        // 4. epilogue at tile end
        if (chunk == 3) {
            float mv0[4], mv1[4];
#pragma unroll
            for (int j = 0; j < 4; j++) {
                int col = wn * 32 + j * 8 + (lane & 3) * 2;
                mv0[j] = sv[col];
                mv1[j] = sv[col + 1];
            }
#pragma unroll
            for (int i = 0; i < 4; i++) {
#pragma unroll
                for (int rh = 0; rh < 2; rh++) {
                    float p = 0.f;
#pragma unroll
                    for (int j = 0; j < 4; j++) {
                        p = fmaf(fast_tanh(c[i][j][rh * 2 + 0]), mv0[j], p);
                        p = fmaf(fast_tanh(c[i][j][rh * 2 + 1]), mv1[j], p);
                    }
                    p += __shfl_xor_sync(0xffffffffu, p, 1);
                    p += __shfl_xor_sync(0xffffffffu, p, 2);
                    if ((lane & 3) == 0)
                        red[(wg * 64 + i * 16 + rh * 8 + (lane >> 2)) * 8 + wn] = p;
                }
            }
            __syncthreads();
            if (tid < 128) {
                float s = 0.f;
#pragma unroll
                for (int w = 0; w < 8; w++) s += red[tid * 8 + w];
                g_scores[(size_t)tile * 128 + tid] = s;
            }
#pragma unroll
            for (int i = 0; i < 4; i++)
#pragma unroll
                for (int j = 0; j < 4; j++)
#pragma unroll
                    for (int r = 0; r < 4; r++) c[i][j][r] = 0.f;
        }

        tile = ntile; chunk = nchunk; par ^= 1;
    }
}

// ---------------- phase 2: softmax over T per batch -------------------------
__global__ void softmax_kernel(float* __restrict__ weights)
{
    const int b   = blockIdx.x;
    const int tid = threadIdx.x;
    const float* s = g_scores + (size_t)b * TT;
    __shared__ float red[256];

    float sc[16];
    float m = -INFINITY;
#pragma unroll
    for (int i = 0; i < 16; i++) {
        sc[i] = s[tid + i * 256];
        m = fmaxf(m, sc[i]);
    }
    red[tid] = m;
    __syncthreads();
    for (int st = 128; st > 0; st >>= 1) {
        if (tid < st) red[tid] = fmaxf(red[tid], red[tid + st]);
        __syncthreads();
    }
    m = red[0];
    __syncthreads();

    float sum = 0.f;
#pragma unroll
    for (int i = 0; i < 16; i++) {
        sc[i] = expf(sc[i] - m);
        sum += sc[i];
    }
    red[tid] = sum;
    __syncthreads();
    for (int st = 128; st > 0; st >>= 1) {
        if (tid < st) red[tid] += red[tid + st];
        __syncthreads();
    }
    const float inv = 1.f / red[0];
#pragma unroll
    for (int i = 0; i < 16; i++)
        weights[(size_t)b * TT + tid + i * 256] = sc[i] * inv;
}

// ---------------- phase 3: context, 2-stage (1024 blocks, float4) ----------
__global__ void __launch_bounds__(256)
ctx_part_kernel(const float* __restrict__ X, const float* __restrict__ w)
{
    const int b   = blockIdx.x;
    const int seg = blockIdx.y;                 // 0..15, 256 timesteps each
    const int q   = threadIdx.x & 63;           // float4 slot over d
    const int tr  = threadIdx.x >> 6;           // 0..3 t-lane
    const float* xb = X + ((size_t)b * TT + seg * 256) * DD + q * 4;
    const float* wb = w + (size_t)b * TT + seg * 256;

    float4 acc = make_float4(0.f, 0.f, 0.f, 0.f);
    for (int it = 0; it < 64; it += 4) {
#pragma unroll
        for (int u2 = 0; u2 < 4; u2++) {
            int t = (it + u2) * 4 + tr;
            float wt = wb[t];
            float4 xv = *(const float4*)(xb + (size_t)t * DD);
            acc.x = fmaf(wt, xv.x, acc.x);
            acc.y = fmaf(wt, xv.y, acc.y);
            acc.z = fmaf(wt, xv.z, acc.z);
            acc.w = fmaf(wt, xv.w, acc.w);
        }
    }

    __shared__ float4 red[256];
    red[threadIdx.x] = acc;
    __syncthreads();
    if (tr == 0) {
        float4 a = red[q], b4 = red[q + 64], c4 = red[q + 128], d4 = red[q + 192];
        float4 r;
        r.x = (a.x + b4.x) + (c4.x + d4.x);
        r.y = (a.y + b4.y) + (c4.y + d4.y);
        r.z = (a.z + b4.z) + (c4.z + d4.z);
        r.w = (a.w + b4.w) + (c4.w + d4.w);
        *(float4*)&g_cpart[((size_t)seg * BB + b) * DD + q * 4] = r;
    }
}

__global__ void ctx_final_kernel(float* __restrict__ ctx)
{
    const int b = blockIdx.x, d = threadIdx.x;
    float s = 0.f;
#pragma unroll
    for (int seg = 0; seg < 16; seg++)
        s += g_cpart[((size_t)seg * BB + b) * DD + d];
    ctx[(size_t)b * DD + d] = s;
}

// ---------------------------------------------------------------------------
extern "C" void kernel_launch(void* const* d_in, const int* in_sizes, int n_in,
                              void* d_out, int out_size)
{
    const float* X  = (const float*)d_in[0];
    const float* W1 = (const float*)d_in[1];
    const float* W2 = (const float*)d_in[2];
    const float* v  = (const float*)d_in[3];

    float* out     = (float*)d_out;
    float* ctx     = out;               // context_vector: B*D floats
    float* weights = out + BB * DD;     // attention_weights: B*T floats

    cudaFuncSetAttribute(score_mma_kernel,
                         cudaFuncAttributeMaxDynamicSharedMemorySize, SM_TOTAL);

    prep_w<<<256, 256>>>(W1, W2);
    score_mma_kernel<<<NSM, 512, SM_TOTAL>>>(X, v);
    softmax_kernel<<<BB, 256>>>(weights);
    ctx_part_kernel<<<dim3(BB, 16), 256>>>(X, weights);
    ctx_final_kernel<<<BB, 256>>>(ctx);
}